// round 2
// baseline (speedup 1.0000x reference)
#include <cuda_runtime.h>
#include <math.h>

#define BB 2
#define TT 2048
#define CC 1024
#define HH 16
#define HD 64

// Scratch (allocation-free rule: __device__ globals)
__device__ float g_q[BB*HH*TT*HD];
__device__ float g_k[BB*HH*TT*HD];
__device__ float g_v[BB*HH*TT*HD];
__device__ float g_y[BB*TT*CC];

// ---------------------------------------------------------------------------
// Fused QKV projection: y = x @ W^T + b, outputs in [B,H,T,HD] layout.
// Tiles: BM=64, BN=64, BK=32. 256 threads, 4x4 micro-tile per thread.
// ---------------------------------------------------------------------------
__global__ __launch_bounds__(256) void qkv_gemm(
    const float* __restrict__ x,
    const float* __restrict__ Wq, const float* __restrict__ bq,
    const float* __restrict__ Wk, const float* __restrict__ bk,
    const float* __restrict__ Wv, const float* __restrict__ bv)
{
    const int BK = 32;
    __shared__ float As[64][36];  // [m][k], row stride 36 floats (144B, 16B-aligned)
    __shared__ float Bs[32][65];  // [k][n], odd pad -> conflict-free transposed stores

    int tid = threadIdx.x;
    int tx = tid & 15, ty = tid >> 4;
    int mbase = blockIdx.y * 64;
    int cb = blockIdx.x * 64;              // global col in [0, 3072)
    int mat = cb >> 10;                    // 0=q, 1=k, 2=v
    int nloc = cb & 1023;

    const float* W    = (mat == 0) ? Wq : (mat == 1) ? Wk : Wv;
    const float* bias = (mat == 0) ? bq : (mat == 1) ? bk : bv;
    float* out        = (mat == 0) ? g_q : (mat == 1) ? g_k : g_v;

    float acc[4][4];
    #pragma unroll
    for (int i = 0; i < 4; i++)
        #pragma unroll
        for (int j = 0; j < 4; j++) acc[i][j] = 0.f;

    int lrow = tid >> 3;            // 0..31
    int lk4  = (tid & 7) * 4;       // 0,4,...,28

    for (int k0 = 0; k0 < CC; k0 += BK) {
        __syncthreads();
        #pragma unroll
        for (int rr = 0; rr < 2; rr++) {
            int r = lrow + rr * 32;
            float4 va = *(const float4*)&x[(size_t)(mbase + r) * CC + k0 + lk4];
            *(float4*)&As[r][lk4] = va;
            float4 vb = *(const float4*)&W[(size_t)(nloc + r) * CC + k0 + lk4];
            Bs[lk4 + 0][r] = vb.x;
            Bs[lk4 + 1][r] = vb.y;
            Bs[lk4 + 2][r] = vb.z;
            Bs[lk4 + 3][r] = vb.w;
        }
        __syncthreads();
        #pragma unroll
        for (int k = 0; k < BK; k++) {
            float a[4], b[4];
            #pragma unroll
            for (int i = 0; i < 4; i++) a[i] = As[ty * 4 + i][k];
            #pragma unroll
            for (int j = 0; j < 4; j++) b[j] = Bs[k][tx * 4 + j];
            #pragma unroll
            for (int i = 0; i < 4; i++)
                #pragma unroll
                for (int j = 0; j < 4; j++)
                    acc[i][j] = fmaf(a[i], b[j], acc[i][j]);
        }
    }

    // Store into [B,H,T,HD]
    #pragma unroll
    for (int i = 0; i < 4; i++) {
        int m = mbase + ty * 4 + i;
        int b = m >> 11;            // /T
        int t = m & (TT - 1);
        #pragma unroll
        for (int j = 0; j < 4; j++) {
            int n = nloc + tx * 4 + j;
            int hh = n >> 6, d = n & 63;
            out[(((size_t)(b * HH + hh) * TT) + t) * HD + d] = acc[i][j] + bias[n];
        }
    }
}

// ---------------------------------------------------------------------------
// Flash attention: per block (q-tile 64, head, batch). 256 threads.
// Thread (r = tid>>2, q4 = tid&3): row r, columns c = q4 + 4*ct (interleaved
// so K smem float4 loads hit distinct bank groups). Q lives in registers.
// P overwrites the K smem buffer after scores are computed.
// ---------------------------------------------------------------------------
__global__ __launch_bounds__(256) void attn_kernel(const float* __restrict__ hbias)
{
    __shared__ float Ks[64][68];   // also reused as P after S is computed
    __shared__ float Vs[64][68];

    int tid = threadIdx.x;
    int r  = tid >> 2;     // 0..63
    int q4 = tid & 3;      // 0..3

    int qt = (int)gridDim.x - 1 - (int)blockIdx.x;  // heavy tiles first
    int hh = blockIdx.y;
    int b  = blockIdx.z;
    int qbase = qt * 64;
    int qg = qbase + r;

    const float* qptr = g_q + (size_t)(b * HH + hh) * TT * HD;
    const float* kptr = g_k + (size_t)(b * HH + hh) * TT * HD;
    const float* vptr = g_v + (size_t)(b * HH + hh) * TT * HD;
    const float* hb   = hbias + (size_t)(b * HH + hh) * TT * TT + (size_t)qg * TT;

    // Q row into registers (redundant x4 across quads; tiny traffic, L1 hit)
    float4 Q[16];
    #pragma unroll
    for (int i = 0; i < 16; i++)
        Q[i] = *(const float4*)&qptr[(size_t)qg * HD + i * 4];

    float m = -INFINITY, l = 0.f;
    float4 O[4];
    #pragma unroll
    for (int i = 0; i < 4; i++) O[i] = make_float4(0.f, 0.f, 0.f, 0.f);

    int ntiles = qt + 1;
    for (int j = 0; j < ntiles; j++) {
        int kb = j * 64;
        __syncthreads();   // previous PV done before overwriting Ks/Vs
        for (int idx = tid; idx < 64 * 16; idx += 256) {
            int row = idx >> 4, d4 = (idx & 15) * 4;
            *(float4*)&Ks[row][d4] = *(const float4*)&kptr[(size_t)(kb + row) * HD + d4];
            *(float4*)&Vs[row][d4] = *(const float4*)&vptr[(size_t)(kb + row) * HD + d4];
        }
        __syncthreads();

        // S = Q K^T (this thread: 16 interleaved columns)
        float s[16];
        #pragma unroll
        for (int c = 0; c < 16; c++) s[c] = 0.f;
        #pragma unroll
        for (int d4 = 0; d4 < 16; d4++) {
            float4 qv = Q[d4];
            #pragma unroll
            for (int c = 0; c < 16; c++) {
                float4 kv = *(const float4*)&Ks[q4 + 4 * c][d4 * 4];
                s[c] = fmaf(qv.x, kv.x,
                       fmaf(qv.y, kv.y,
                       fmaf(qv.z, kv.z,
                       fmaf(qv.w, kv.w, s[c]))));
            }
        }

        // bias + causal mask + tile max
        float mt = -INFINITY;
        #pragma unroll
        for (int c = 0; c < 16; c++) {
            int kg = kb + q4 + 4 * c;
            float val = s[c] * 0.125f + hb[kg];
            if (kg > qg) val = -INFINITY;
            s[c] = val;
            mt = fmaxf(mt, val);
        }
        mt = fmaxf(mt, __shfl_xor_sync(0xffffffffu, mt, 1));
        mt = fmaxf(mt, __shfl_xor_sync(0xffffffffu, mt, 2));

        float mnew = fmaxf(m, mt);
        float alpha = __expf(m - mnew);   // first tile: exp(-inf)=0
        float lsum = 0.f;
        #pragma unroll
        for (int c = 0; c < 16; c++) {
            float p = __expf(s[c] - mnew);
            s[c] = p;
            lsum += p;
        }
        lsum += __shfl_xor_sync(0xffffffffu, lsum, 1);
        lsum += __shfl_xor_sync(0xffffffffu, lsum, 2);
        l = l * alpha + lsum;
        m = mnew;
        #pragma unroll
        for (int i = 0; i < 4; i++) {
            O[i].x *= alpha; O[i].y *= alpha; O[i].z *= alpha; O[i].w *= alpha;
        }

        __syncthreads();   // all reads of Ks finished
        #pragma unroll
        for (int c = 0; c < 16; c++) Ks[r][q4 + 4 * c] = s[c];  // P into K buffer
        __syncthreads();

        // O += P V  (this thread: d = q4*4 + 16*i .. +3, interleaved)
        #pragma unroll 8
        for (int c = 0; c < 64; c++) {
            float p = Ks[r][c];
            #pragma unroll
            for (int i = 0; i < 4; i++) {
                float4 vv = *(const float4*)&Vs[c][q4 * 4 + 16 * i];
                O[i].x = fmaf(p, vv.x, O[i].x);
                O[i].y = fmaf(p, vv.y, O[i].y);
                O[i].z = fmaf(p, vv.z, O[i].z);
                O[i].w = fmaf(p, vv.w, O[i].w);
            }
        }
    }

    float inv = 1.f / l;
    float* yout = g_y + ((size_t)b * TT + qg) * CC + hh * HD;
    #pragma unroll
    for (int i = 0; i < 4; i++) {
        O[i].x *= inv; O[i].y *= inv; O[i].z *= inv; O[i].w *= inv;
        *(float4*)&yout[q4 * 4 + 16 * i] = O[i];
    }
}

// ---------------------------------------------------------------------------
// Output projection: out = g_y @ Wp^T + bp   ([4096,1024] x [1024,1024])
// ---------------------------------------------------------------------------
__global__ __launch_bounds__(256) void proj_gemm(
    const float* __restrict__ Wp, const float* __restrict__ bp,
    float* __restrict__ out)
{
    const int BK = 32;
    __shared__ float As[64][36];
    __shared__ float Bs[32][65];

    int tid = threadIdx.x;
    int tx = tid & 15, ty = tid >> 4;
    int mbase = blockIdx.y * 64;
    int nbase = blockIdx.x * 64;

    float acc[4][4];
    #pragma unroll
    for (int i = 0; i < 4; i++)
        #pragma unroll
        for (int j = 0; j < 4; j++) acc[i][j] = 0.f;

    int lrow = tid >> 3;
    int lk4  = (tid & 7) * 4;

    for (int k0 = 0; k0 < CC; k0 += BK) {
        __syncthreads();
        #pragma unroll
        for (int rr = 0; rr < 2; rr++) {
            int r = lrow + rr * 32;
            float4 va = *(const float4*)&g_y[(size_t)(mbase + r) * CC + k0 + lk4];
            *(float4*)&As[r][lk4] = va;
            float4 vb = *(const float4*)&Wp[(size_t)(nbase + r) * CC + k0 + lk4];
            Bs[lk4 + 0][r] = vb.x;
            Bs[lk4 + 1][r] = vb.y;
            Bs[lk4 + 2][r] = vb.z;
            Bs[lk4 + 3][r] = vb.w;
        }
        __syncthreads();
        #pragma unroll
        for (int k = 0; k < BK; k++) {
            float a[4], b[4];
            #pragma unroll
            for (int i = 0; i < 4; i++) a[i] = As[ty * 4 + i][k];
            #pragma unroll
            for (int j = 0; j < 4; j++) b[j] = Bs[k][tx * 4 + j];
            #pragma unroll
            for (int i = 0; i < 4; i++)
                #pragma unroll
                for (int j = 0; j < 4; j++)
                    acc[i][j] = fmaf(a[i], b[j], acc[i][j]);
        }
    }

    #pragma unroll
    for (int i = 0; i < 4; i++) {
        int mrow = mbase + ty * 4 + i;
        #pragma unroll
        for (int j = 0; j < 4; j++) {
            int n = nbase + tx * 4 + j;
            out[(size_t)mrow * CC + n] = acc[i][j] + bp[n];
        }
    }
}

// ---------------------------------------------------------------------------
extern "C" void kernel_launch(void* const* d_in, const int* in_sizes, int n_in,
                              void* d_out, int out_size)
{
    const float* x  = (const float*)d_in[0];
    const float* h  = (const float*)d_in[1];
    const float* Wq = (const float*)d_in[2];
    const float* bq = (const float*)d_in[3];
    const float* Wk = (const float*)d_in[4];
    const float* bk = (const float*)d_in[5];
    const float* Wv = (const float*)d_in[6];
    const float* bv = (const float*)d_in[7];
    const float* Wp = (const float*)d_in[8];
    const float* bp = (const float*)d_in[9];
    float* out = (float*)d_out;

    dim3 g1(48, 64);          // N=3072, M=4096 in 64x64 tiles
    qkv_gemm<<<g1, 256>>>(x, Wq, bq, Wk, bk, Wv, bv);

    dim3 g2(TT / 64, HH, BB); // 32 x 16 x 2
    attn_kernel<<<g2, 256>>>(h);

    dim3 g3(16, 64);          // N=1024, M=4096
    proj_gemm<<<g3, 256>>>(Wp, bp, out);
}

// round 3
// speedup vs baseline: 4.3829x; 4.3829x over previous
#include <cuda_runtime.h>
#include <math.h>

#define BB 2
#define TT 2048
#define CC 1024
#define HH 16
#define HD 64

// Scratch (allocation-free rule: __device__ globals)
__device__ float g_q[BB*HH*TT*HD];
__device__ float g_k[BB*HH*TT*HD];
__device__ float g_v[BB*HH*TT*HD];
__device__ float g_y[BB*TT*CC];

// ---------------------------------------------------------------------------
// helpers
// ---------------------------------------------------------------------------
__device__ __forceinline__ unsigned f2tf(float f) {
    unsigned u;
    asm("cvt.rna.tf32.f32 %0, %1;" : "=r"(u) : "f"(f));
    return u;
}

// D = A(16x8 tf32, row) * B(8x8 tf32, col) + D, fp32 accum
__device__ __forceinline__ void mma8(float* c, const unsigned* a, const unsigned* b) {
    asm volatile(
        "mma.sync.aligned.m16n8k8.row.col.f32.tf32.tf32.f32 "
        "{%0,%1,%2,%3},{%4,%5,%6,%7},{%8,%9},{%0,%1,%2,%3};"
        : "+f"(c[0]), "+f"(c[1]), "+f"(c[2]), "+f"(c[3])
        : "r"(a[0]), "r"(a[1]), "r"(a[2]), "r"(a[3]), "r"(b[0]), "r"(b[1]));
}

// ---------------------------------------------------------------------------
// QKV projection (tensor core): y = x @ W^T + b  -> [B,H,T,HD]
// Block 128x128, BK=32, 8 warps (2m x 4n), warp tile 64x32.
// ---------------------------------------------------------------------------
__global__ __launch_bounds__(256) void qkv_gemm_tc(
    const float* __restrict__ x,
    const float* __restrict__ Wq, const float* __restrict__ bq,
    const float* __restrict__ Wk, const float* __restrict__ bk,
    const float* __restrict__ Wv, const float* __restrict__ bv)
{
    __shared__ unsigned As[128][36];   // [m][k] tf32
    __shared__ unsigned Bs[128][36];   // [n][k] tf32

    int tid = threadIdx.x;
    int lane = tid & 31, warp = tid >> 5;
    int g = lane >> 2, t4 = lane & 3;
    int wm = warp >> 2;                // 0..1
    int wn = warp & 3;                 // 0..3

    int mbase = blockIdx.y * 128;
    int cb = blockIdx.x * 128;         // 0..2944 (step 128, no matrix crossing)
    int mat = cb >> 10;
    int nloc = cb & 1023;

    const float* W    = (mat == 0) ? Wq : (mat == 1) ? Wk : Wv;
    const float* bias = (mat == 0) ? bq : (mat == 1) ? bk : bv;
    float* out        = (mat == 0) ? g_q : (mat == 1) ? g_k : g_v;

    float acc[4][4][4];
    #pragma unroll
    for (int mt = 0; mt < 4; mt++)
        #pragma unroll
        for (int nt = 0; nt < 4; nt++)
            #pragma unroll
            for (int i = 0; i < 4; i++) acc[mt][nt][i] = 0.f;

    int lrow = tid >> 3;               // 0..31
    int lc4  = (tid & 7) * 4;          // 0..28

    for (int k0 = 0; k0 < CC; k0 += 32) {
        __syncthreads();
        #pragma unroll
        for (int i = 0; i < 4; i++) {
            int row = lrow + i * 32;
            float4 va = *(const float4*)&x[(size_t)(mbase + row) * CC + k0 + lc4];
            As[row][lc4 + 0] = f2tf(va.x);
            As[row][lc4 + 1] = f2tf(va.y);
            As[row][lc4 + 2] = f2tf(va.z);
            As[row][lc4 + 3] = f2tf(va.w);
            float4 vb = *(const float4*)&W[(size_t)(nloc + row) * CC + k0 + lc4];
            Bs[row][lc4 + 0] = f2tf(vb.x);
            Bs[row][lc4 + 1] = f2tf(vb.y);
            Bs[row][lc4 + 2] = f2tf(vb.z);
            Bs[row][lc4 + 3] = f2tf(vb.w);
        }
        __syncthreads();

        #pragma unroll
        for (int k8 = 0; k8 < 4; k8++) {
            int kc = k8 * 8 + t4;
            unsigned a[4][4], b[4][2];
            #pragma unroll
            for (int mt = 0; mt < 4; mt++) {
                int mr = wm * 64 + mt * 16 + g;
                a[mt][0] = As[mr][kc];
                a[mt][1] = As[mr + 8][kc];
                a[mt][2] = As[mr][kc + 4];
                a[mt][3] = As[mr + 8][kc + 4];
            }
            #pragma unroll
            for (int nt = 0; nt < 4; nt++) {
                int nr = wn * 32 + nt * 8 + g;
                b[nt][0] = Bs[nr][kc];
                b[nt][1] = Bs[nr][kc + 4];
            }
            #pragma unroll
            for (int mt = 0; mt < 4; mt++)
                #pragma unroll
                for (int nt = 0; nt < 4; nt++)
                    mma8(acc[mt][nt], a[mt], b[nt]);
        }
    }

    // epilogue: bias + store into [B,H,T,HD]
    #pragma unroll
    for (int mt = 0; mt < 4; mt++) {
        int m0 = mbase + wm * 64 + mt * 16 + g;
        #pragma unroll
        for (int nt = 0; nt < 4; nt++) {
            int n0 = nloc + wn * 32 + nt * 8 + 2 * t4;
            int hh = n0 >> 6, d0 = n0 & 63;
            #pragma unroll
            for (int rr = 0; rr < 2; rr++) {
                int m = m0 + rr * 8;
                int bidx = m >> 11, t = m & (TT - 1);
                float2 v;
                v.x = acc[mt][nt][rr * 2 + 0] + bias[n0];
                v.y = acc[mt][nt][rr * 2 + 1] + bias[n0 + 1];
                *(float2*)&out[(((size_t)(bidx * HH + hh) * TT) + t) * HD + d0] = v;
            }
        }
    }
}

// ---------------------------------------------------------------------------
// Flash attention (tensor core). 128 threads = 4 warps; warp w owns q rows
// [qt*64 + 16w, +16). Q frags in regs; K/V tf32 in smem; P reuses K buffer.
// ---------------------------------------------------------------------------
__global__ __launch_bounds__(128) void attn_tc(const float* __restrict__ hbias)
{
    __shared__ unsigned Ks[64][68];   // K tile, then reused for P
    __shared__ unsigned Vs[64][68];

    int tid = threadIdx.x;
    int lane = tid & 31, warp = tid >> 5;
    int g = lane >> 2, t4 = lane & 3;

    int qt = (int)gridDim.x - 1 - (int)blockIdx.x;  // heavy tiles first
    int hh = blockIdx.y;
    int b  = blockIdx.z;
    int qbase = qt * 64;
    int qrow = qbase + warp * 16;      // warp's first q row (global)
    int qg0 = qrow + g;
    int qg1 = qg0 + 8;

    const float* qptr = g_q + (size_t)(b * HH + hh) * TT * HD;
    const float* kptr = g_k + (size_t)(b * HH + hh) * TT * HD;
    const float* vptr = g_v + (size_t)(b * HH + hh) * TT * HD;
    const float* hb0  = hbias + (size_t)(b * HH + hh) * TT * TT + (size_t)qg0 * TT;
    const float* hb1  = hb0 + (size_t)8 * TT;

    // Q fragments: [d8][4]
    unsigned qa[8][4];
    #pragma unroll
    for (int d8 = 0; d8 < 8; d8++) {
        int dc = d8 * 8 + t4;
        qa[d8][0] = f2tf(qptr[(size_t)qg0 * HD + dc]);
        qa[d8][1] = f2tf(qptr[(size_t)qg1 * HD + dc]);
        qa[d8][2] = f2tf(qptr[(size_t)qg0 * HD + dc + 4]);
        qa[d8][3] = f2tf(qptr[(size_t)qg1 * HD + dc + 4]);
    }

    float m0 = -INFINITY, m1 = -INFINITY, l0 = 0.f, l1 = 0.f;
    float O[8][4];
    #pragma unroll
    for (int nt = 0; nt < 8; nt++)
        #pragma unroll
        for (int i = 0; i < 4; i++) O[nt][i] = 0.f;

    int ntiles = qt + 1;
    for (int j = 0; j < ntiles; j++) {
        int kb = j * 64;
        __syncthreads();   // prior PV reads of Ks/Vs done
        for (int idx = tid; idx < 64 * 16; idx += 128) {
            int row = idx >> 4, c4 = (idx & 15) * 4;
            float4 kv = *(const float4*)&kptr[(size_t)(kb + row) * HD + c4];
            Ks[row][c4 + 0] = f2tf(kv.x);
            Ks[row][c4 + 1] = f2tf(kv.y);
            Ks[row][c4 + 2] = f2tf(kv.z);
            Ks[row][c4 + 3] = f2tf(kv.w);
            float4 vv = *(const float4*)&vptr[(size_t)(kb + row) * HD + c4];
            Vs[row][c4 + 0] = f2tf(vv.x);
            Vs[row][c4 + 1] = f2tf(vv.y);
            Vs[row][c4 + 2] = f2tf(vv.z);
            Vs[row][c4 + 3] = f2tf(vv.w);
        }
        __syncthreads();

        // S = Q K^T : per nt an 16x8 tile over kk
        float s[8][4];
        #pragma unroll
        for (int nt = 0; nt < 8; nt++) {
            s[nt][0] = s[nt][1] = s[nt][2] = s[nt][3] = 0.f;
            #pragma unroll
            for (int d8 = 0; d8 < 8; d8++) {
                int dc = d8 * 8 + t4;
                unsigned bb_[2];
                bb_[0] = Ks[nt * 8 + g][dc];
                bb_[1] = Ks[nt * 8 + g][dc + 4];
                mma8(s[nt], qa[d8], bb_);
            }
        }

        __syncthreads();   // all warps done reading Ks before P overwrites it

        // scale + h-bias + causal mask + row max
        float mt0 = -INFINITY, mt1 = -INFINITY;
        #pragma unroll
        for (int nt = 0; nt < 8; nt++) {
            int kg = kb + nt * 8 + 2 * t4;
            float2 h0 = *(const float2*)&hb0[kg];
            float2 h1 = *(const float2*)&hb1[kg];
            s[nt][0] = (kg     <= qg0) ? s[nt][0] * 0.125f + h0.x : -INFINITY;
            s[nt][1] = (kg + 1 <= qg0) ? s[nt][1] * 0.125f + h0.y : -INFINITY;
            s[nt][2] = (kg     <= qg1) ? s[nt][2] * 0.125f + h1.x : -INFINITY;
            s[nt][3] = (kg + 1 <= qg1) ? s[nt][3] * 0.125f + h1.y : -INFINITY;
            mt0 = fmaxf(mt0, fmaxf(s[nt][0], s[nt][1]));
            mt1 = fmaxf(mt1, fmaxf(s[nt][2], s[nt][3]));
        }
        mt0 = fmaxf(mt0, __shfl_xor_sync(0xffffffffu, mt0, 1));
        mt0 = fmaxf(mt0, __shfl_xor_sync(0xffffffffu, mt0, 2));
        mt1 = fmaxf(mt1, __shfl_xor_sync(0xffffffffu, mt1, 1));
        mt1 = fmaxf(mt1, __shfl_xor_sync(0xffffffffu, mt1, 2));

        float mn0 = fmaxf(m0, mt0), mn1 = fmaxf(m1, mt1);
        float al0 = __expf(m0 - mn0), al1 = __expf(m1 - mn1);
        float ls0 = 0.f, ls1 = 0.f;
        #pragma unroll
        for (int nt = 0; nt < 8; nt++) {
            s[nt][0] = __expf(s[nt][0] - mn0);
            s[nt][1] = __expf(s[nt][1] - mn0);
            s[nt][2] = __expf(s[nt][2] - mn1);
            s[nt][3] = __expf(s[nt][3] - mn1);
            ls0 += s[nt][0] + s[nt][1];
            ls1 += s[nt][2] + s[nt][3];
        }
        ls0 += __shfl_xor_sync(0xffffffffu, ls0, 1);
        ls0 += __shfl_xor_sync(0xffffffffu, ls0, 2);
        ls1 += __shfl_xor_sync(0xffffffffu, ls1, 1);
        ls1 += __shfl_xor_sync(0xffffffffu, ls1, 2);
        l0 = l0 * al0 + ls0;  m0 = mn0;
        l1 = l1 * al1 + ls1;  m1 = mn1;
        #pragma unroll
        for (int nt = 0; nt < 8; nt++) {
            O[nt][0] *= al0; O[nt][1] *= al0;
            O[nt][2] *= al1; O[nt][3] *= al1;
        }

        // P (tf32) into Ks rows [warp*16, +16)
        int pr0 = warp * 16 + g;
        #pragma unroll
        for (int nt = 0; nt < 8; nt++) {
            int c = nt * 8 + 2 * t4;
            Ks[pr0][c]     = f2tf(s[nt][0]);
            Ks[pr0][c + 1] = f2tf(s[nt][1]);
            Ks[pr0 + 8][c]     = f2tf(s[nt][2]);
            Ks[pr0 + 8][c + 1] = f2tf(s[nt][3]);
        }
        __syncwarp();

        // O += P V
        #pragma unroll
        for (int k8 = 0; k8 < 8; k8++) {
            int kc = k8 * 8 + t4;
            unsigned ap[4];
            ap[0] = Ks[warp * 16 + g][kc];
            ap[1] = Ks[warp * 16 + g + 8][kc];
            ap[2] = Ks[warp * 16 + g][kc + 4];
            ap[3] = Ks[warp * 16 + g + 8][kc + 4];
            #pragma unroll
            for (int nt = 0; nt < 8; nt++) {
                unsigned bb_[2];
                bb_[0] = Vs[kc][nt * 8 + g];
                bb_[1] = Vs[kc + 4][nt * 8 + g];
                mma8(O[nt], ap, bb_);
            }
        }
    }

    float inv0 = 1.f / l0, inv1 = 1.f / l1;
    float* y0 = g_y + ((size_t)b * TT + qg0) * CC + hh * HD;
    float* y1 = g_y + ((size_t)b * TT + qg1) * CC + hh * HD;
    #pragma unroll
    for (int nt = 0; nt < 8; nt++) {
        int d = nt * 8 + 2 * t4;
        float2 v0; v0.x = O[nt][0] * inv0; v0.y = O[nt][1] * inv0;
        float2 v1; v1.x = O[nt][2] * inv1; v1.y = O[nt][3] * inv1;
        *(float2*)&y0[d] = v0;
        *(float2*)&y1[d] = v1;
    }
}

// ---------------------------------------------------------------------------
// Output projection (tensor core): out = g_y @ Wp^T + bp
// ---------------------------------------------------------------------------
__global__ __launch_bounds__(256) void proj_gemm_tc(
    const float* __restrict__ Wp, const float* __restrict__ bp,
    float* __restrict__ out)
{
    __shared__ unsigned As[128][36];
    __shared__ unsigned Bs[128][36];

    int tid = threadIdx.x;
    int lane = tid & 31, warp = tid >> 5;
    int g = lane >> 2, t4 = lane & 3;
    int wm = warp >> 2;
    int wn = warp & 3;

    int mbase = blockIdx.y * 128;
    int nbase = blockIdx.x * 128;

    float acc[4][4][4];
    #pragma unroll
    for (int mt = 0; mt < 4; mt++)
        #pragma unroll
        for (int nt = 0; nt < 4; nt++)
            #pragma unroll
            for (int i = 0; i < 4; i++) acc[mt][nt][i] = 0.f;

    int lrow = tid >> 3;
    int lc4  = (tid & 7) * 4;

    for (int k0 = 0; k0 < CC; k0 += 32) {
        __syncthreads();
        #pragma unroll
        for (int i = 0; i < 4; i++) {
            int row = lrow + i * 32;
            float4 va = *(const float4*)&g_y[(size_t)(mbase + row) * CC + k0 + lc4];
            As[row][lc4 + 0] = f2tf(va.x);
            As[row][lc4 + 1] = f2tf(va.y);
            As[row][lc4 + 2] = f2tf(va.z);
            As[row][lc4 + 3] = f2tf(va.w);
            float4 vb = *(const float4*)&Wp[(size_t)(nbase + row) * CC + k0 + lc4];
            Bs[row][lc4 + 0] = f2tf(vb.x);
            Bs[row][lc4 + 1] = f2tf(vb.y);
            Bs[row][lc4 + 2] = f2tf(vb.z);
            Bs[row][lc4 + 3] = f2tf(vb.w);
        }
        __syncthreads();

        #pragma unroll
        for (int k8 = 0; k8 < 4; k8++) {
            int kc = k8 * 8 + t4;
            unsigned a[4][4], b[4][2];
            #pragma unroll
            for (int mt = 0; mt < 4; mt++) {
                int mr = wm * 64 + mt * 16 + g;
                a[mt][0] = As[mr][kc];
                a[mt][1] = As[mr + 8][kc];
                a[mt][2] = As[mr][kc + 4];
                a[mt][3] = As[mr + 8][kc + 4];
            }
            #pragma unroll
            for (int nt = 0; nt < 4; nt++) {
                int nr = wn * 32 + nt * 8 + g;
                b[nt][0] = Bs[nr][kc];
                b[nt][1] = Bs[nr][kc + 4];
            }
            #pragma unroll
            for (int mt = 0; mt < 4; mt++)
                #pragma unroll
                for (int nt = 0; nt < 4; nt++)
                    mma8(acc[mt][nt], a[mt], b[nt]);
        }
    }

    #pragma unroll
    for (int mt = 0; mt < 4; mt++) {
        int m0 = mbase + wm * 64 + mt * 16 + g;
        #pragma unroll
        for (int nt = 0; nt < 4; nt++) {
            int n0 = nbase + wn * 32 + nt * 8 + 2 * t4;
            #pragma unroll
            for (int rr = 0; rr < 2; rr++) {
                int m = m0 + rr * 8;
                float2 v;
                v.x = acc[mt][nt][rr * 2 + 0] + bp[n0];
                v.y = acc[mt][nt][rr * 2 + 1] + bp[n0 + 1];
                *(float2*)&out[(size_t)m * CC + n0] = v;
            }
        }
    }
}

// ---------------------------------------------------------------------------
extern "C" void kernel_launch(void* const* d_in, const int* in_sizes, int n_in,
                              void* d_out, int out_size)
{
    const float* x  = (const float*)d_in[0];
    const float* h  = (const float*)d_in[1];
    const float* Wq = (const float*)d_in[2];
    const float* bq = (const float*)d_in[3];
    const float* Wk = (const float*)d_in[4];
    const float* bk = (const float*)d_in[5];
    const float* Wv = (const float*)d_in[6];
    const float* bv = (const float*)d_in[7];
    const float* Wp = (const float*)d_in[8];
    const float* bp = (const float*)d_in[9];
    float* out = (float*)d_out;

    dim3 g1(24, 32);            // N=3072, M=4096 in 128x128 tiles
    qkv_gemm_tc<<<g1, 256>>>(x, Wq, bq, Wk, bk, Wv, bv);

    dim3 g2(TT / 64, HH, BB);   // 32 x 16 x 2
    attn_tc<<<g2, 128>>>(h);

    dim3 g3(8, 32);             // N=1024, M=4096
    proj_gemm_tc<<<g3, 256>>>(Wp, bp, out);
}